// round 10
// baseline (speedup 1.0000x reference)
#include <cuda_runtime.h>
#include <cuda_bf16.h>
#include <cstdint>

#define BB 128
#define TT 1024
#define EE 512
#define HH 1024
#define VV 512
#define NB 128
#define NT 512
#define BH (BB*HH)
#define BTV ((size_t)BB*TT*VV)

// smem layout (offsets from 1KB-aligned base)
#define SB_G   0          // 64KB: G B-slabs: chunk(0..3)*16384 + term*8192
#define SB_EA  65536      // 32KB: P1a B-slabs: chunk(0..1)*16384 + term*8192
#define SB_EY  98304      // 16KB: logits B-slab: term*8192
#define AB0    114688     // A double buffer 2 x 32KB
#define ABSZ   32768
#define DYNB_ALLOC (AB0 + 2*ABSZ + 1024)

__device__ __align__(16) float g_tokproj[VV * HH];
__device__ __align__(16) float g_P0p[4][BH];             // G: K=256 slices
__device__ __align__(16) float g_P1bp[4][BH];            // G
__device__ __align__(16) float g_P1ap[2][8][BH];         // E: parity x K=128 slices
__device__ __align__(16) float g_Py[2][16][BB * VV];     // E: parity x K=64 slices
__device__ __align__(16) __nv_bfloat16 g_h0sp[2][2][BH]; // parity x term
__device__ __align__(16) __nv_bfloat16 g_h1sp[2][2][BH];
__device__ __align__(16) __nv_bfloat16 g_w0sp[2][HH * HH];
__device__ __align__(16) __nv_bfloat16 g_w1sp[2][HH * HH];
__device__ __align__(16) __nv_bfloat16 g_w2sp[2][HH * HH];
__device__ __align__(16) __nv_bfloat16 g_wysp[2][VV * HH];
__device__ unsigned long long g_arr8[8];
__device__ unsigned long long g_epoch[NB];

__device__ __forceinline__ uint32_t smem_u32(const void* p) {
    uint32_t a;
    asm("{ .reg .u64 t; cvta.to.shared.u64 t, %1; cvt.u32.u64 %0, t; }" : "=r"(a) : "l"(p));
    return a;
}
__device__ __forceinline__ void cp16(uint32_t dst, const void* src) {
    asm volatile("cp.async.cg.shared.global [%0], [%1], 16;" :: "r"(dst), "l"(src) : "memory");
}
#define CP_COMMIT() asm volatile("cp.async.commit_group;" ::: "memory")
#define CP_WAIT1()  asm volatile("cp.async.wait_group 1;" ::: "memory")
#define CP_WAIT0()  asm volatile("cp.async.wait_group 0;" ::: "memory")
#define STS128(a, x, y, z, w) \
    asm volatile("st.shared.v4.b32 [%0], {%1,%2,%3,%4};" \
                 :: "r"(a), "r"(x), "r"(y), "r"(z), "r"(w) : "memory")
#define LDSM4(r, a) \
    asm volatile("ldmatrix.sync.aligned.m8n8.x4.shared.b16 {%0,%1,%2,%3}, [%4];" \
        : "=r"((r)[0]), "=r"((r)[1]), "=r"((r)[2]), "=r"((r)[3]) : "r"(a))
#define MMA16816(c, a, b0r, b1r) \
    asm volatile("mma.sync.aligned.m16n8k16.row.col.f32.bf16.bf16.f32 " \
        "{%0,%1,%2,%3}, {%4,%5,%6,%7}, {%8,%9}, {%0,%1,%2,%3};" \
        : "+f"((c)[0]), "+f"((c)[1]), "+f"((c)[2]), "+f"((c)[3]) \
        : "r"((a)[0]), "r"((a)[1]), "r"((a)[2]), "r"((a)[3]), "r"(b0r), "r"(b1r))

__device__ __forceinline__ void grid_bar(unsigned long long& epoch) {
    epoch += (unsigned long long)NB;
    __syncthreads();
    if (threadIdx.x == 0) {
        __threadfence();
        atomicAdd(&g_arr8[blockIdx.x & 7], 1ULL);
        for (;;) {
            unsigned long long s = 0;
#pragma unroll
            for (int i = 0; i < 8; i++) s += *(volatile unsigned long long*)&g_arr8[i];
            if (s >= epoch) break;
            __nanosleep(32);
        }
        __threadfence();
    }
    __syncthreads();
}

__device__ __forceinline__ void split2(float x, __nv_bfloat16& d0, __nv_bfloat16& d1) {
    __nv_bfloat16 b0 = __float2bfloat16(x);
    d0 = b0;
    d1 = __float2bfloat16(x - __bfloat162float(b0));
}
__device__ __forceinline__ void st_split2(__nv_bfloat16* d0, __nv_bfloat16* d1,
                                          size_t idx, float2 v) {
    __nv_bfloat16 a0, b0, a1, b1;
    split2(v.x, a0, b0); split2(v.y, a1, b1);
    __nv_bfloat162 t0(a0, a1), t1(b0, b1);
    *(uint32_t*)(d0 + idx) = *(uint32_t*)&t0;
    *(uint32_t*)(d1 + idx) = *(uint32_t*)&t1;
}

// SIMT fp32 64x64 GEMM (tokproj prologue only, NT=512)
template <typename LA, typename LB, typename ST>
__device__ __forceinline__ void gemm64(float* sA, float* sB, int kend, LA la, LB lb, ST st) {
    const int tid = threadIdx.x;
    const int tx = tid & 15, ty = tid >> 4;
    float acc[2][4];
#pragma unroll
    for (int i = 0; i < 2; i++)
#pragma unroll
        for (int j = 0; j < 4; j++) acc[i][j] = 0.f;
    for (int k0 = 0; k0 < kend; k0 += 32) {
#pragma unroll
        for (int i = 0; i < 4; i++) {
            int idx = tid + i * NT;
            int k = idx & 31, r = idx >> 5;
            sA[k * 68 + r] = la(r, k0 + k);
            sB[k * 68 + r] = lb(r, k0 + k);
        }
        __syncthreads();
#pragma unroll
        for (int kk = 0; kk < 32; kk++) {
            float2 a = *(const float2*)(sA + kk * 68 + 2 * ty);
            float4 b = *(const float4*)(sB + kk * 68 + 4 * tx);
#pragma unroll
            for (int i = 0; i < 2; i++) {
                float av = i ? a.y : a.x;
                acc[i][0] = fmaf(av, b.x, acc[i][0]);
                acc[i][1] = fmaf(av, b.y, acc[i][1]);
                acc[i][2] = fmaf(av, b.z, acc[i][2]);
                acc[i][3] = fmaf(av, b.w, acc[i][3]);
            }
        }
        __syncthreads();
    }
#pragma unroll
    for (int i = 0; i < 2; i++)
        st(2 * ty + i, 4 * tx, make_float4(acc[i][0], acc[i][1], acc[i][2], acc[i][3]));
}

// stage one A chunk: 2 terms x 128 rows x 64 K-cols -> 32KB
__device__ __forceinline__ void stage_a(uint32_t ab, const __nv_bfloat16* A0,
                                        const __nv_bfloat16* A1, int kg) {
    const int tid = threadIdx.x;
#pragma unroll
    for (int it = 0; it < 4; it++) {
        int id = tid + it * NT;
        int i = id >> 10, rem = id & 1023, r = rem >> 3, seg = rem & 7;
        const __nv_bfloat16* s = (i ? A1 : A0) + (size_t)r * HH + kg + seg * 8;
        cp16(ab + i * 16384 + r * 128 + ((seg ^ (r & 7)) << 4), s);
    }
    CP_COMMIT();
}

// one K=64 chunk of 3-term MMA into acc[2][2][4]; 16 warps = 4M x 4N, warp tile 32x16
__device__ __forceinline__ void chunk_mma(float acc[2][2][4], uint32_t ab, uint32_t pb,
                                          int wm, int wn, int lane) {
#pragma unroll
    for (int kk = 0; kk < 4; kk++) {
        uint32_t af[2][2][4];
#pragma unroll
        for (int tm = 0; tm < 2; tm++)
#pragma unroll
            for (int mt = 0; mt < 2; mt++) {
                int row = wm * 32 + mt * 16 + (lane & 15);
                int ch = kk * 2 + (lane >> 4);
                LDSM4(af[tm][mt], ab + tm * 16384 + row * 128 + ((ch ^ (row & 7)) << 4));
            }
        uint32_t bf[2][4];
#pragma unroll
        for (int j = 0; j < 2; j++) {
            int nrow = wn * 16 + (lane & 7) + ((lane & 16) ? 8 : 0);
            int ch = kk * 2 + ((lane >> 3) & 1);
            LDSM4(bf[j], pb + j * 8192 + nrow * 128 + ((ch ^ (nrow & 7)) << 4));
        }
#pragma unroll
        for (int j = 0; j < 2; j++) {
            const int ni = (j == 0) ? 2 : 1;   // terms: a0b0, a1b0, a0b1
#pragma unroll
            for (int i = 0; i < 2; i++) {
                if (i >= ni) break;
#pragma unroll
                for (int mt = 0; mt < 2; mt++)
#pragma unroll
                    for (int nt = 0; nt < 2; nt++)
                        MMA16816(acc[mt][nt], af[i][mt], bf[j][nt * 2], bf[j][nt * 2 + 1]);
            }
        }
    }
}

__device__ __forceinline__ void store_acc(float acc[2][2][4], float* pd, int stride,
                                          int n0, int wm, int wn, int lane) {
#pragma unroll
    for (int mt = 0; mt < 2; mt++)
#pragma unroll
        for (int nt = 0; nt < 2; nt++) {
            int r = wm * 32 + mt * 16 + (lane >> 2);
            int cc = wn * 16 + nt * 8 + (lane & 3) * 2;
            *(float2*)(pd + (size_t)r * stride + n0 + cc) =
                make_float2(acc[mt][nt][0], acc[mt][nt][1]);
            *(float2*)(pd + (size_t)(r + 8) * stride + n0 + cc) =
                make_float2(acc[mt][nt][2], acc[mt][nt][3]);
        }
}

__global__ void __launch_bounds__(NT, 1) rnn_mma_kernel(
    const int*   __restrict__ ids,   const float* __restrict__ emb,
    const float* __restrict__ w_xh0, const float* __restrict__ w_hh0,
    const float* __restrict__ b_h0,  const float* __restrict__ w_xh1,
    const float* __restrict__ w_hh1, const float* __restrict__ b_h1,
    const float* __restrict__ w_hy,  const float* __restrict__ b_y,
    float* __restrict__ out, long long out_size)
{
    extern __shared__ __align__(16) char dynsm[];
    const int bid = blockIdx.x;
    const int tid = threadIdx.x;
    const int lane = tid & 31;
    const int warp = tid >> 5;
    const int wm = warp >> 2, wn = warp & 3;
    const uint32_t dyn = (smem_u32(dynsm) + 1023u) & ~1023u;
    const long long full = (long long)BTV + 2LL * BH;

    unsigned long long epoch = g_epoch[bid];

    // G job: gemm gG (0:P0/w_hh0, 1:P1b/w_hh1), n-tile, K=256 slice
    const int gG  = bid >> 6;
    const int nG0 = ((bid >> 2) & 15) * 64;
    const int kcG = bid & 3;
    const int kbegG = kcG * 256;
    // E jobs: P1a (16n x 8kc, K=128), logits (8n x 16kc, K=64)
    const int nA0 = (bid >> 3) * 64;
    const int kcA = bid & 7;
    const int kA  = kcA * 128;
    const int nY0 = (bid >> 4) * 64;
    const int kcY = bid & 15;
    const int kY  = kcY * 64;

    // ============ prologue ============
    {
        const float* W[4] = {w_hh0, w_xh1, w_hh1, w_hy};
        __nv_bfloat16* S0[4] = {g_w0sp[0], g_w1sp[0], g_w2sp[0], g_wysp[0]};
        __nv_bfloat16* S1[4] = {g_w0sp[1], g_w1sp[1], g_w2sp[1], g_wysp[1]};
        const int SZ[4] = {HH * HH, HH * HH, HH * HH, VV * HH};
#pragma unroll
        for (int w = 0; w < 4; w++)
            for (int i = bid * NT + tid; i < SZ[w]; i += NB * NT)
                split2(W[w][i], S0[w][i], S1[w][i]);
        for (int i = bid * NT + tid; i < BH; i += NB * NT) {  // P1b zeros for h1_0
            g_P1bp[0][i] = 0.f; g_P1bp[1][i] = 0.f;
            g_P1bp[2][i] = 0.f; g_P1bp[3][i] = 0.f;
        }
    }
    {
        float* sA = (float*)dynsm;
        float* sB = sA + 32 * 68;
        int m0 = (bid & 7) * 64, n0t = (bid >> 3) * 64;
        gemm64(sA, sB, EE,
            [&](int r, int k) { return emb[(m0 + r) * EE + k]; },
            [&](int r, int k) { return w_xh0[(n0t + r) * EE + k]; },
            [&](int m, int n, float4 v) {
                int col = n0t + n;
                float4 bb = *(const float4*)(b_h0 + col);
                v.x += bb.x; v.y += bb.y; v.z += bb.z; v.w += bb.w;
                *(float4*)(g_tokproj + (size_t)(m0 + m) * HH + col) = v;
            });
    }
    grid_bar(epoch);

    // persistent B slabs (loaded once)
    {
        const __nv_bfloat16* WG0 = gG ? g_w2sp[0] : g_w0sp[0];
        const __nv_bfloat16* WG1 = gG ? g_w2sp[1] : g_w0sp[1];
        for (int x = tid; x < 4096; x += NT) {
            int c = x >> 10, rem = x & 1023, j = rem >> 9, r = (rem >> 3) & 63, seg = x & 7;
            const __nv_bfloat16* s = (j ? WG1 : WG0)
                + (size_t)(nG0 + r) * HH + kbegG + c * 64 + seg * 8;
            uint4 v = *(const uint4*)s;
            STS128(dyn + SB_G + c * 16384 + j * 8192 + r * 128 + ((seg ^ (r & 7)) << 4),
                   v.x, v.y, v.z, v.w);
        }
        for (int x = tid; x < 2048; x += NT) {
            int c = x >> 10, rem = x & 1023, j = rem >> 9, r = (rem >> 3) & 63, seg = x & 7;
            const __nv_bfloat16* s = (j ? g_w1sp[1] : g_w1sp[0])
                + (size_t)(nA0 + r) * HH + kA + c * 64 + seg * 8;
            uint4 v = *(const uint4*)s;
            STS128(dyn + SB_EA + c * 16384 + j * 8192 + r * 128 + ((seg ^ (r & 7)) << 4),
                   v.x, v.y, v.z, v.w);
        }
        for (int x = tid; x < 1024; x += NT) {
            int j = x >> 9, rem = x & 511, r = rem >> 3, seg = x & 7;
            const __nv_bfloat16* s = (j ? g_wysp[1] : g_wysp[0])
                + (size_t)(nY0 + r) * HH + kY + seg * 8;
            uint4 v = *(const uint4*)s;
            STS128(dyn + SB_EY + j * 8192 + r * 128 + ((seg ^ (r & 7)) << 4),
                   v.x, v.y, v.z, v.w);
        }
        __syncthreads();
    }

    // ============ main loop ============
    for (int t = 0; t <= TT + 3; t++) {
        const int pw = t & 1;
        const int pr = pw ^ 1;

        // ---------- E phase ----------
        const bool doA = (t >= 1 && t <= TT);        // P1a_{t-1} from h0_{t-1}
        const bool doY = (t >= 3 && t <= TT + 2);    // Py_{t-3} from h1_{t-3}
        int m = 0;
        const __nv_bfloat16 *ca0[3], *ca1[3];
        int ck[3]; uint32_t cb[3]; int cq[3];
        if (doA) {
            ca0[0] = g_h0sp[pr][0]; ca1[0] = g_h0sp[pr][1];
            ck[0] = kA;      cb[0] = dyn + SB_EA;         cq[0] = 0;
            ca0[1] = g_h0sp[pr][0]; ca1[1] = g_h0sp[pr][1];
            ck[1] = kA + 64; cb[1] = dyn + SB_EA + 16384; cq[1] = 0;
            m = 2;
        }
        if (doY) {
            ca0[m] = g_h1sp[pr][0]; ca1[m] = g_h1sp[pr][1];
            ck[m] = kY; cb[m] = dyn + SB_EY; cq[m] = 1; m++;
        }
        if (m > 0) stage_a(dyn + AB0, ca0[0], ca1[0], ck[0]);
        if (m > 1) stage_a(dyn + AB0 + ABSZ, ca0[1], ca1[1], ck[1]);

        // elementwise (overlaps in-flight cp.async)
        {
            const int i2 = tid * 2;
            const size_t idx = (size_t)bid * HH + i2;
            if (t <= TT - 1) {                 // h0_t
                const int id_tok = ids[bid * TT + t];
                float2 s = *(const float2*)(g_tokproj + (size_t)id_tok * HH + i2);
                if (t > 0) {
#pragma unroll
                    for (int k = 0; k < 4; k++) {
                        float2 p = __ldcg((const float2*)&g_P0p[k][idx]);
                        s.x += p.x; s.y += p.y;
                    }
                }
                float2 v = make_float2(tanhf(s.x), tanhf(s.y));
                st_split2(g_h0sp[pw][0], g_h0sp[pw][1], idx, v);
                if (t == TT - 1 && out_size >= full) *(float2*)&out[BTV + idx] = v;
            }
            if (t >= 2 && t <= TT + 1) {       // h1_{t-2}
                float2 s = *(const float2*)(b_h1 + i2);
#pragma unroll
                for (int k = 0; k < 8; k++) {
                    float2 p = __ldcg((const float2*)&g_P1ap[pr][k][idx]);
                    s.x += p.x; s.y += p.y;
                }
#pragma unroll
                for (int k = 0; k < 4; k++) {
                    float2 p = __ldcg((const float2*)&g_P1bp[k][idx]);
                    s.x += p.x; s.y += p.y;
                }
                float2 v = make_float2(tanhf(s.x), tanhf(s.y));
                st_split2(g_h1sp[pw][0], g_h1sp[pw][1], idx, v);
                if (t == TT + 1 && out_size >= full) *(float2*)&out[BTV + BH + idx] = v;
            }
            if (t >= 4) {                      // logits row t-4
                const size_t pidx = (size_t)bid * VV + tid;
                float r = b_y[tid];
#pragma unroll
                for (int k = 0; k < 16; k++) r += __ldcg(&g_Py[pr][k][pidx]);
                out[((size_t)bid * TT + (t - 4)) * VV + tid] = r;
            }
        }

        // E-phase MMA quanta
        if (m > 0) {
            float accA[2][2][4], accY[2][2][4];
#pragma unroll
            for (int a = 0; a < 2; a++)
#pragma unroll
                for (int b = 0; b < 2; b++)
#pragma unroll
                    for (int c = 0; c < 4; c++) { accA[a][b][c] = 0.f; accY[a][b][c] = 0.f; }
            for (int c = 0; c < m; c++) {
                if (c + 1 < m) { CP_WAIT1(); } else { CP_WAIT0(); }
                __syncthreads();
                chunk_mma(cq[c] ? accY : accA, dyn + AB0 + (c & 1) * ABSZ, cb[c],
                          wm, wn, lane);
                __syncthreads();
                if (c + 2 < m) stage_a(dyn + AB0 + (c & 1) * ABSZ,
                                       ca0[c + 2], ca1[c + 2], ck[c + 2]);
            }
            if (doA) store_acc(accA, &g_P1ap[pw][kcA][0], HH, nA0, wm, wn, lane);
            if (doY) store_acc(accY, &g_Py[pw][kcY][0], VV, nY0, wm, wn, lane);
        }
        grid_bar(epoch);

        // ---------- G phase ----------
        const bool doG = gG ? (t >= 2 && t <= TT) : (t <= TT - 2);
        if (doG) {
            const __nv_bfloat16* A0 = gG ? g_h1sp[pw][0] : g_h0sp[pw][0];
            const __nv_bfloat16* A1 = gG ? g_h1sp[pw][1] : g_h0sp[pw][1];
            float acc[2][2][4];
#pragma unroll
            for (int a = 0; a < 2; a++)
#pragma unroll
                for (int b = 0; b < 2; b++)
#pragma unroll
                    for (int c = 0; c < 4; c++) acc[a][b][c] = 0.f;
            stage_a(dyn + AB0, A0, A1, kbegG);
            stage_a(dyn + AB0 + ABSZ, A0, A1, kbegG + 64);
            for (int c = 0; c < 4; c++) {
                if (c < 3) { CP_WAIT1(); } else { CP_WAIT0(); }
                __syncthreads();
                chunk_mma(acc, dyn + AB0 + (c & 1) * ABSZ, dyn + SB_G + c * 16384,
                          wm, wn, lane);
                __syncthreads();
                if (c < 2) stage_a(dyn + AB0 + (c & 1) * ABSZ, A0, A1,
                                   kbegG + (c + 2) * 64);
            }
            store_acc(acc, gG ? &g_P1bp[kcG][0] : &g_P0p[kcG][0], HH, nG0, wm, wn, lane);
        }
        grid_bar(epoch);
    }

    if (tid == 0) g_epoch[bid] = epoch;
}

extern "C" void kernel_launch(void* const* d_in, const int* in_sizes, int n_in,
                              void* d_out, int out_size) {
    const int*   ids   = (const int*)d_in[0];
    const float* emb   = (const float*)d_in[1];
    const float* w_xh0 = (const float*)d_in[2];
    const float* w_hh0 = (const float*)d_in[3];
    const float* b_h0  = (const float*)d_in[4];
    const float* w_xh1 = (const float*)d_in[5];
    const float* w_hh1 = (const float*)d_in[6];
    const float* b_h1  = (const float*)d_in[7];
    const float* w_hy  = (const float*)d_in[8];
    const float* b_y   = (const float*)d_in[9];
    float* out = (float*)d_out;

    cudaFuncSetAttribute(rnn_mma_kernel, cudaFuncAttributeMaxDynamicSharedMemorySize,
                         DYNB_ALLOC);
    rnn_mma_kernel<<<NB, NT, DYNB_ALLOC>>>(ids, emb, w_xh0, w_hh0, b_h0,
                                           w_xh1, w_hh1, b_h1, w_hy, b_y,
                                           out, (long long)out_size);
}

// round 11
// speedup vs baseline: 1.3388x; 1.3388x over previous
#include <cuda_runtime.h>
#include <cuda_bf16.h>
#include <cstdint>

#define BB 128
#define TT 1024
#define EE 512
#define HH 1024
#define VV 512
#define NB 128
#define NT 256
#define BH (BB*HH)
#define BTV ((size_t)BB*TT*VV)

// smem: persistent B at 0 (up to 4 chunks x 32KB), A double buffer after
#define BCH    32768           // one B chunk: 2 terms x 128 rows x 128B
#define AB0    131072
#define ABSZ   32768           // A chunk: 2 terms x 128 rows x 128B
#define DYNB_ALLOC (AB0 + 2*ABSZ + 1024)

__device__ __align__(16) float g_tokproj[VV * HH];
__device__ __align__(16) float g_P0p[4][BH];            // h0 preact partials, kc slices
__device__ __align__(16) float g_P1p[8][BH];            // h1 preact partials (P1a 0-3, P1b 4-7)
__device__ __align__(16) float g_Py[8][BB * VV];        // logits partials
__device__ __align__(16) __nv_bfloat16 g_h0sp[2][BH];   // term
__device__ __align__(16) __nv_bfloat16 g_h1sp[2][BH];
__device__ __align__(16) __nv_bfloat16 g_w0sp[2][HH * HH];
__device__ __align__(16) __nv_bfloat16 g_w1sp[2][HH * HH];
__device__ __align__(16) __nv_bfloat16 g_w2sp[2][HH * HH];
__device__ __align__(16) __nv_bfloat16 g_wysp[2][VV * HH];
__device__ unsigned long long g_arr8[8];
__device__ unsigned long long g_epoch[NB];

__device__ __forceinline__ uint32_t smem_u32(const void* p) {
    uint32_t a;
    asm("{ .reg .u64 t; cvta.to.shared.u64 t, %1; cvt.u32.u64 %0, t; }" : "=r"(a) : "l"(p));
    return a;
}
__device__ __forceinline__ void cp16(uint32_t dst, const void* src) {
    asm volatile("cp.async.cg.shared.global [%0], [%1], 16;" :: "r"(dst), "l"(src) : "memory");
}
#define CP_COMMIT() asm volatile("cp.async.commit_group;" ::: "memory")
#define CP_WAIT1()  asm volatile("cp.async.wait_group 1;" ::: "memory")
#define CP_WAIT0()  asm volatile("cp.async.wait_group 0;" ::: "memory")
#define STS128(a, x, y, z, w) \
    asm volatile("st.shared.v4.b32 [%0], {%1,%2,%3,%4};" \
                 :: "r"(a), "r"(x), "r"(y), "r"(z), "r"(w) : "memory")
#define LDSM4(r, a) \
    asm volatile("ldmatrix.sync.aligned.m8n8.x4.shared.b16 {%0,%1,%2,%3}, [%4];" \
        : "=r"((r)[0]), "=r"((r)[1]), "=r"((r)[2]), "=r"((r)[3]) : "r"(a))
#define MMA16816(c, a, b0r, b1r) \
    asm volatile("mma.sync.aligned.m16n8k16.row.col.f32.bf16.bf16.f32 " \
        "{%0,%1,%2,%3}, {%4,%5,%6,%7}, {%8,%9}, {%0,%1,%2,%3};" \
        : "+f"((c)[0]), "+f"((c)[1]), "+f"((c)[2]), "+f"((c)[3]) \
        : "r"((a)[0]), "r"((a)[1]), "r"((a)[2]), "r"((a)[3]), "r"(b0r), "r"(b1r))

__device__ __forceinline__ void grid_bar(unsigned long long& epoch) {
    epoch += (unsigned long long)NB;
    __syncthreads();
    if (threadIdx.x == 0) {
        __threadfence();
        atomicAdd(&g_arr8[blockIdx.x & 7], 1ULL);
        for (;;) {
            unsigned long long s = 0;
#pragma unroll
            for (int i = 0; i < 8; i++) s += *(volatile unsigned long long*)&g_arr8[i];
            if (s >= epoch) break;
            __nanosleep(32);
        }
        __threadfence();
    }
    __syncthreads();
}

__device__ __forceinline__ void split2(float x, __nv_bfloat16& d0, __nv_bfloat16& d1) {
    __nv_bfloat16 b0 = __float2bfloat16(x);
    d0 = b0;
    d1 = __float2bfloat16(x - __bfloat162float(b0));
}
__device__ __forceinline__ void st_split4(__nv_bfloat16* d0, __nv_bfloat16* d1,
                                          size_t idx, float4 v) {
    __nv_bfloat16 a0, b0, a1, b1, a2, b2, a3, b3;
    split2(v.x, a0, b0); split2(v.y, a1, b1);
    split2(v.z, a2, b2); split2(v.w, a3, b3);
    __nv_bfloat162 lo0(a0, a1), hi0(a2, a3), lo1(b0, b1), hi1(b2, b3);
    *(uint2*)(d0 + idx) = make_uint2(*(uint32_t*)&lo0, *(uint32_t*)&hi0);
    *(uint2*)(d1 + idx) = make_uint2(*(uint32_t*)&lo1, *(uint32_t*)&hi1);
}

// SIMT fp32 64x64 GEMM (tokproj prologue only, NT=256)
template <typename LA, typename LB, typename ST>
__device__ __forceinline__ void gemm64(float* sA, float* sB, int kend, LA la, LB lb, ST st) {
    const int tid = threadIdx.x;
    const int tx = tid & 15, ty = tid >> 4;
    float acc[4][4];
#pragma unroll
    for (int i = 0; i < 4; i++)
#pragma unroll
        for (int j = 0; j < 4; j++) acc[i][j] = 0.f;
    for (int k0 = 0; k0 < kend; k0 += 32) {
#pragma unroll
        for (int i = 0; i < 8; i++) {
            int idx = tid + i * NT;
            int k = idx & 31, r = idx >> 5;
            sA[k * 68 + r] = la(r, k0 + k);
            sB[k * 68 + r] = lb(r, k0 + k);
        }
        __syncthreads();
#pragma unroll
        for (int kk = 0; kk < 32; kk++) {
            float4 a = *(const float4*)(sA + kk * 68 + 4 * ty);
            float4 b = *(const float4*)(sB + kk * 68 + 4 * tx);
            float av[4] = {a.x, a.y, a.z, a.w};
            float bv[4] = {b.x, b.y, b.z, b.w};
#pragma unroll
            for (int i = 0; i < 4; i++)
#pragma unroll
                for (int j = 0; j < 4; j++) acc[i][j] = fmaf(av[i], bv[j], acc[i][j]);
        }
        __syncthreads();
    }
#pragma unroll
    for (int i = 0; i < 4; i++)
        st(4 * ty + i, 4 * tx, make_float4(acc[i][0], acc[i][1], acc[i][2], acc[i][3]));
}

// stage one A chunk: 2 terms x 128 rows x 64 K-cols -> 32KB
__device__ __forceinline__ void stage_a(uint32_t ab, const __nv_bfloat16* A0,
                                        const __nv_bfloat16* A1, int kg) {
    const int tid = threadIdx.x;
#pragma unroll
    for (int it = 0; it < 8; it++) {
        int id = tid + it * NT;                       // 0..2047
        int i = id >> 10, rem = id & 1023, r = rem >> 3, seg = rem & 7;
        const __nv_bfloat16* s = (i ? A1 : A0) + (size_t)r * HH + kg + seg * 8;
        cp16(ab + i * 16384 + r * 128 + ((seg ^ (r & 7)) << 4), s);
    }
    CP_COMMIT();
}

// one K=64 chunk of 3-term MMA; 8 warps = 2M x 4N, warp tile 64x32
__device__ __forceinline__ void chunk_mma(float acc[4][4][4], uint32_t ab, uint32_t pb,
                                          int wm, int wn, int lane) {
#pragma unroll
    for (int kk = 0; kk < 4; kk++) {
        uint32_t af[2][4][4];
#pragma unroll
        for (int tm = 0; tm < 2; tm++)
#pragma unroll
            for (int mt = 0; mt < 4; mt++) {
                int row = wm * 64 + mt * 16 + (lane & 15);
                int ch = kk * 2 + (lane >> 4);
                LDSM4(af[tm][mt], ab + tm * 16384 + row * 128 + ((ch ^ (row & 7)) << 4));
            }
        uint32_t bf[2][8];
#pragma unroll
        for (int j = 0; j < 2; j++)
#pragma unroll
            for (int q = 0; q < 2; q++) {
                int nrow = wn * 32 + q * 16 + (lane & 7) + ((lane & 16) ? 8 : 0);
                int ch = kk * 2 + ((lane >> 3) & 1);
                LDSM4(&bf[j][q * 4], pb + j * 16384 + nrow * 128 + ((ch ^ (nrow & 7)) << 4));
            }
#pragma unroll
        for (int j = 0; j < 2; j++) {
            const int ni = (j == 0) ? 2 : 1;          // terms: a0b0, a1b0, a0b1
#pragma unroll
            for (int i = 0; i < 2; i++) {
                if (i >= ni) break;
#pragma unroll
                for (int mt = 0; mt < 4; mt++)
#pragma unroll
                    for (int nt = 0; nt < 4; nt++) {
                        int q = nt >> 1, o = (nt & 1) * 2;
                        MMA16816(acc[mt][nt], af[i][mt], bf[j][q * 4 + o], bf[j][q * 4 + o + 1]);
                    }
            }
        }
    }
}

__global__ void __launch_bounds__(NT, 1) rnn_mma_kernel(
    const int*   __restrict__ ids,   const float* __restrict__ emb,
    const float* __restrict__ w_xh0, const float* __restrict__ w_hh0,
    const float* __restrict__ b_h0,  const float* __restrict__ w_xh1,
    const float* __restrict__ w_hh1, const float* __restrict__ b_h1,
    const float* __restrict__ w_hy,  const float* __restrict__ b_y,
    float* __restrict__ out, long long out_size)
{
    extern __shared__ __align__(16) char dynsm[];
    const int bid = blockIdx.x;
    const int tid = threadIdx.x;
    const int lane = tid & 31;
    const int warp = tid >> 5;
    const int wm = warp >> 2, wn = warp & 3;         // 2M x 4N, warp tile 64x32
    const uint32_t dyn = (smem_u32(dynsm) + 1023u) & ~1023u;
    const long long full = (long long)BTV + 2LL * BH;

    unsigned long long epoch = g_epoch[bid];

    // ---- fixed job assignment (job tile 128 x 128) ----
    // role 0: bid 0..31   P0  = h0 @ w_hh0^T  (8 n-tiles x 4 kc, K=256)
    // role 1: bid 32..63  P1a = h0 @ w_xh1^T
    // role 2: bid 64..95  P1b = h1 @ w_hh1^T
    // role 3: bid 96..127 LOG = h1 @ w_hy^T   (4 n-tiles x 8 kc, K=128)
    const int role = bid >> 5;
    int n0, kbeg, nch, pstride;
    const __nv_bfloat16 *Bs0, *Bs1;
    float* pdst;
    if (role == 0) {
        n0 = (bid & 7) * 128; int kc = (bid >> 3) & 3;
        kbeg = kc * 256; nch = 4; Bs0 = g_w0sp[0]; Bs1 = g_w0sp[1];
        pdst = g_P0p[kc]; pstride = HH;
    } else if (role == 1) {
        int j = bid - 32; n0 = (j & 7) * 128; int kc = (j >> 3) & 3;
        kbeg = kc * 256; nch = 4; Bs0 = g_w1sp[0]; Bs1 = g_w1sp[1];
        pdst = g_P1p[kc]; pstride = HH;
    } else if (role == 2) {
        int j = bid - 64; n0 = (j & 7) * 128; int kc = (j >> 3) & 3;
        kbeg = kc * 256; nch = 4; Bs0 = g_w2sp[0]; Bs1 = g_w2sp[1];
        pdst = g_P1p[4 + kc]; pstride = HH;
    } else {
        int j = bid - 96; n0 = (j & 3) * 128; int kc = (j >> 2) & 7;
        kbeg = kc * 128; nch = 2; Bs0 = g_wysp[0]; Bs1 = g_wysp[1];
        pdst = g_Py[kc]; pstride = VV;
    }

    // ============ prologue ============
    {
        const float* W[4] = {w_hh0, w_xh1, w_hh1, w_hy};
        __nv_bfloat16* S0[4] = {g_w0sp[0], g_w1sp[0], g_w2sp[0], g_wysp[0]};
        __nv_bfloat16* S1[4] = {g_w0sp[1], g_w1sp[1], g_w2sp[1], g_wysp[1]};
        const int SZ[4] = {HH * HH, HH * HH, HH * HH, VV * HH};
#pragma unroll
        for (int w = 0; w < 4; w++)
            for (int i = bid * NT + tid; i < SZ[w]; i += NB * NT)
                split2(W[w][i], S0[w][i], S1[w][i]);
        for (int i = bid * NT + tid; i < BH; i += NB * NT) {   // h1_{-1} = 0
            g_h1sp[0][i] = __float2bfloat16(0.f);
            g_h1sp[1][i] = __float2bfloat16(0.f);
        }
    }
    {   // tokproj[v][h] = b_h0[h] + emb[v] . w_xh0[h]
        float* sA = (float*)dynsm;
        float* sB = sA + 32 * 68;
        int m0 = (bid & 7) * 64, n0t = (bid >> 3) * 64;
        gemm64(sA, sB, EE,
            [&](int r, int k) { return emb[(m0 + r) * EE + k]; },
            [&](int r, int k) { return w_xh0[(n0t + r) * EE + k]; },
            [&](int m, int n, float4 v) {
                int col = n0t + n;
                float4 bb = *(const float4*)(b_h0 + col);
                v.x += bb.x; v.y += bb.y; v.z += bb.z; v.w += bb.w;
                *(float4*)(g_tokproj + (size_t)(m0 + m) * HH + col) = v;
            });
    }
    grid_bar(epoch);

    // ---- persistent B slabs (loaded once): nch chunks x 2 terms x 128 rows ----
    {
        const int total = nch * 2048;
        for (int x = tid; x < total; x += NT) {
            int c = x >> 11, rem = x & 2047;
            int j = rem >> 10, r = (rem >> 3) & 127, seg = x & 7;
            const __nv_bfloat16* s = (j ? Bs1 : Bs0)
                + (size_t)(n0 + r) * HH + kbeg + c * 64 + seg * 8;
            uint4 v = *(const uint4*)s;
            STS128(dyn + c * BCH + j * 16384 + r * 128 + ((seg ^ (r & 7)) << 4),
                   v.x, v.y, v.z, v.w);
        }
        __syncthreads();
    }

    // ============ main loop: t = 0 .. TT ============
    for (int t = 0; t <= TT; t++) {
        // ---- E phase (block = batch row bid) ----
        {
            const int i = tid * 4;
            const size_t idx = (size_t)bid * HH + i;
            if (t >= 1) {                  // h1_{t-1} = tanh(b_h1 + sum8 P1p)
                float4 bb = *(const float4*)(b_h1 + i);
                float4 s = bb;
#pragma unroll
                for (int k = 0; k < 8; k++) {
                    float4 p = __ldcg((const float4*)&g_P1p[k][idx]);
                    s.x += p.x; s.y += p.y; s.z += p.z; s.w += p.w;
                }
                float4 v;
                v.x = tanhf(s.x); v.y = tanhf(s.y); v.z = tanhf(s.z); v.w = tanhf(s.w);
                st_split4(g_h1sp[0], g_h1sp[1], idx, v);
                if (t == TT && out_size >= full)
                    *(float4*)&out[BTV + BH + idx] = v;            // final h1
            }
            if (t < TT) {                  // h0_t = tanh(tokproj + sum4 P0p)
                const int id_tok = ids[bid * TT + t];
                float4 s = *(const float4*)(g_tokproj + (size_t)id_tok * HH + i);
                if (t > 0) {
#pragma unroll
                    for (int k = 0; k < 4; k++) {
                        float4 p = __ldcg((const float4*)&g_P0p[k][idx]);
                        s.x += p.x; s.y += p.y; s.z += p.z; s.w += p.w;
                    }
                }
                float4 v;
                v.x = tanhf(s.x); v.y = tanhf(s.y); v.z = tanhf(s.z); v.w = tanhf(s.w);
                st_split4(g_h0sp[0], g_h0sp[1], idx, v);
                if (t == TT - 1 && out_size >= full)
                    *(float4*)&out[BTV + idx] = v;                 // final h0
            }
            if (t >= 2) {                  // logits row t-2 (2 elems/thread)
                const int v0 = tid * 2;
                const size_t pidx = (size_t)bid * VV + v0;
                float2 r = *(const float2*)(b_y + v0);
#pragma unroll
                for (int k = 0; k < 8; k++) {
                    float2 p = __ldcg((const float2*)&g_Py[k][pidx]);
                    r.x += p.x; r.y += p.y;
                }
                *(float2*)&out[((size_t)bid * TT + (t - 2)) * VV + v0] = r;
            }
        }
        grid_bar(epoch);

        // ---- G phase ----
        bool doG;
        const __nv_bfloat16 *A0, *A1;
        if (role == 0)      { doG = (t < TT - 1); A0 = g_h0sp[0]; A1 = g_h0sp[1]; }
        else if (role == 1) { doG = (t < TT);     A0 = g_h0sp[0]; A1 = g_h0sp[1]; }
        else if (role == 2) { doG = (t < TT);     A0 = g_h1sp[0]; A1 = g_h1sp[1]; }
        else                { doG = true;         A0 = g_h1sp[0]; A1 = g_h1sp[1]; }
        if (doG) {
            float acc[4][4][4];
#pragma unroll
            for (int a = 0; a < 4; a++)
#pragma unroll
                for (int b = 0; b < 4; b++)
#pragma unroll
                    for (int c = 0; c < 4; c++) acc[a][b][c] = 0.f;
            stage_a(dyn + AB0, A0, A1, kbeg);
            if (nch > 1) stage_a(dyn + AB0 + ABSZ, A0, A1, kbeg + 64);
            for (int c = 0; c < nch; c++) {
                if (c + 1 < nch) { CP_WAIT1(); } else { CP_WAIT0(); }
                __syncthreads();
                chunk_mma(acc, dyn + AB0 + (c & 1) * ABSZ, dyn + c * BCH, wm, wn, lane);
                __syncthreads();
                if (c + 2 < nch) stage_a(dyn + AB0 + (c & 1) * ABSZ, A0, A1,
                                         kbeg + (c + 2) * 64);
            }
#pragma unroll
            for (int mt = 0; mt < 4; mt++)
#pragma unroll
                for (int nt = 0; nt < 4; nt++) {
                    int r = wm * 64 + mt * 16 + (lane >> 2);
                    int cc = wn * 32 + nt * 8 + (lane & 3) * 2;
                    *(float2*)(pdst + (size_t)r * pstride + n0 + cc) =
                        make_float2(acc[mt][nt][0], acc[mt][nt][1]);
                    *(float2*)(pdst + (size_t)(r + 8) * pstride + n0 + cc) =
                        make_float2(acc[mt][nt][2], acc[mt][nt][3]);
                }
        }
        grid_bar(epoch);
    }

    // ---- post-loop: logits row TT-1 ----
    {
        const int v0 = tid * 2;
        const size_t pidx = (size_t)bid * VV + v0;
        float2 r = *(const float2*)(b_y + v0);
#pragma unroll
        for (int k = 0; k < 8; k++) {
            float2 p = __ldcg((const float2*)&g_Py[k][pidx]);
            r.x += p.x; r.y += p.y;
        }
        *(float2*)&out[((size_t)bid * TT + (TT - 1)) * VV + v0] = r;
    }
    if (tid == 0) g_epoch[bid] = epoch;
}

extern "C" void kernel_launch(void* const* d_in, const int* in_sizes, int n_in,
                              void* d_out, int out_size) {
    const int*   ids   = (const int*)d_in[0];
    const float* emb   = (const float*)d_in[1];
    const float* w_xh0 = (const float*)d_in[2];
    const float* w_hh0 = (const float*)d_in[3];
    const float* b_h0  = (const float*)d_in[4];
    const float* w_xh1 = (const float*)d_in[5];
    const float* w_hh1 = (const float*)d_in[6];
    const float* b_h1  = (const float*)d_in[7];
    const float* w_hy  = (const float*)d_in[8];
    const float* b_y   = (const float*)d_in[9];
    float* out = (float*)d_out;

    cudaFuncSetAttribute(rnn_mma_kernel, cudaFuncAttributeMaxDynamicSharedMemorySize,
                         DYNB_ALLOC);
    rnn_mma_kernel<<<NB, NT, DYNB_ALLOC>>>(ids, emb, w_xh0, w_hh0, b_h0,
                                           w_xh1, w_hh1, b_h1, w_hy, b_y,
                                           out, (long long)out_size);
}

// round 12
// speedup vs baseline: 1.4028x; 1.0478x over previous
#include <cuda_runtime.h>
#include <cuda_bf16.h>
#include <cstdint>

#define BB 128
#define TT 1024
#define EE 512
#define HH 1024
#define VV 512
#define NB 128
#define NT 256
#define BH (BB*HH)
#define BTV ((size_t)BB*TT*VV)

#define BCH    32768           // one persistent-B chunk: 2 terms x 128 rows x 128B
#define AB0    131072          // A staging after persistent B
#define ABSZ   32768
#define DYNB_ALLOC (AB0 + 2*ABSZ + 1024)

__device__ __align__(16) float g_tokproj[VV * HH];
__device__ __align__(16) float g_P0p[4][BH];
__device__ __align__(16) float g_P1p[8][BH];            // P1a 0-3, P1b 4-7
__device__ __align__(16) float g_Py[8][BB * VV];
__device__ __align__(16) __nv_bfloat16 g_h0ring[4][2][BH];  // ring slot x term
__device__ __align__(16) __nv_bfloat16 g_h1sp[2][BH];
__device__ __align__(16) __nv_bfloat16 g_w0sp[2][HH * HH];
__device__ __align__(16) __nv_bfloat16 g_w1sp[2][HH * HH];
__device__ __align__(16) __nv_bfloat16 g_w2sp[2][HH * HH];
__device__ __align__(16) __nv_bfloat16 g_wysp[2][VV * HH];
__device__ unsigned long long g_brA[8], g_brB[8], g_brF[8];
__device__ unsigned long long g_epA[NB], g_epB[NB], g_epF[NB];
__device__ unsigned long long g_h0done, g_h1done, g_h0base, g_h1base;

__device__ __forceinline__ uint32_t smem_u32(const void* p) {
    uint32_t a;
    asm("{ .reg .u64 t; cvta.to.shared.u64 t, %1; cvt.u32.u64 %0, t; }" : "=r"(a) : "l"(p));
    return a;
}
__device__ __forceinline__ void cp16(uint32_t dst, const void* src) {
    asm volatile("cp.async.cg.shared.global [%0], [%1], 16;" :: "r"(dst), "l"(src) : "memory");
}
#define CP_COMMIT() asm volatile("cp.async.commit_group;" ::: "memory")
#define CP_WAIT1()  asm volatile("cp.async.wait_group 1;" ::: "memory")
#define CP_WAIT0()  asm volatile("cp.async.wait_group 0;" ::: "memory")
#define STS128(a, x, y, z, w) \
    asm volatile("st.shared.v4.b32 [%0], {%1,%2,%3,%4};" \
                 :: "r"(a), "r"(x), "r"(y), "r"(z), "r"(w) : "memory")
#define LDSM4(r, a) \
    asm volatile("ldmatrix.sync.aligned.m8n8.x4.shared.b16 {%0,%1,%2,%3}, [%4];" \
        : "=r"((r)[0]), "=r"((r)[1]), "=r"((r)[2]), "=r"((r)[3]) : "r"(a))
#define MMA16816(c, a, b0r, b1r) \
    asm volatile("mma.sync.aligned.m16n8k16.row.col.f32.bf16.bf16.f32 " \
        "{%0,%1,%2,%3}, {%4,%5,%6,%7}, {%8,%9}, {%0,%1,%2,%3};" \
        : "+f"((c)[0]), "+f"((c)[1]), "+f"((c)[2]), "+f"((c)[3]) \
        : "r"((a)[0]), "r"((a)[1]), "r"((a)[2]), "r"((a)[3]), "r"(b0r), "r"(b1r))

__device__ __forceinline__ void gbar(unsigned long long* ctr, int idx8,
                                     unsigned long long& ep, int delta) {
    ep += (unsigned long long)delta;
    __syncthreads();
    if (threadIdx.x == 0) {
        __threadfence();
        atomicAdd(&ctr[idx8], 1ULL);
        for (;;) {
            unsigned long long s = 0;
#pragma unroll
            for (int i = 0; i < 8; i++) s += *(volatile unsigned long long*)&ctr[i];
            if (s >= ep) break;
            __nanosleep(32);
        }
        __threadfence();
    }
    __syncthreads();
}
__device__ __forceinline__ void wait_ge(unsigned long long* w, unsigned long long v) {
    if (threadIdx.x == 0) {
        while (*(volatile unsigned long long*)w < v) { __nanosleep(32); }
        __threadfence();
    }
    __syncthreads();
}

__device__ __forceinline__ void split2(float x, __nv_bfloat16& d0, __nv_bfloat16& d1) {
    __nv_bfloat16 b0 = __float2bfloat16(x);
    d0 = b0;
    d1 = __float2bfloat16(x - __bfloat162float(b0));
}
__device__ __forceinline__ void st_split4(__nv_bfloat16* d0, __nv_bfloat16* d1,
                                          size_t idx, float4 v) {
    __nv_bfloat16 a0, b0, a1, b1, a2, b2, a3, b3;
    split2(v.x, a0, b0); split2(v.y, a1, b1);
    split2(v.z, a2, b2); split2(v.w, a3, b3);
    __nv_bfloat162 lo0(a0, a1), hi0(a2, a3), lo1(b0, b1), hi1(b2, b3);
    *(uint2*)(d0 + idx) = make_uint2(*(uint32_t*)&lo0, *(uint32_t*)&hi0);
    *(uint2*)(d1 + idx) = make_uint2(*(uint32_t*)&lo1, *(uint32_t*)&hi1);
}

// SIMT fp32 64x64 GEMM (tokproj prologue only)
template <typename LA, typename LB, typename ST>
__device__ __forceinline__ void gemm64(float* sA, float* sB, int kend, LA la, LB lb, ST st) {
    const int tid = threadIdx.x;
    const int tx = tid & 15, ty = tid >> 4;
    float acc[4][4];
#pragma unroll
    for (int i = 0; i < 4; i++)
#pragma unroll
        for (int j = 0; j < 4; j++) acc[i][j] = 0.f;
    for (int k0 = 0; k0 < kend; k0 += 32) {
#pragma unroll
        for (int i = 0; i < 8; i++) {
            int idx = tid + i * NT;
            int k = idx & 31, r = idx >> 5;
            sA[k * 68 + r] = la(r, k0 + k);
            sB[k * 68 + r] = lb(r, k0 + k);
        }
        __syncthreads();
#pragma unroll
        for (int kk = 0; kk < 32; kk++) {
            float4 a = *(const float4*)(sA + kk * 68 + 4 * ty);
            float4 b = *(const float4*)(sB + kk * 68 + 4 * tx);
            float av[4] = {a.x, a.y, a.z, a.w};
            float bv[4] = {b.x, b.y, b.z, b.w};
#pragma unroll
            for (int i = 0; i < 4; i++)
#pragma unroll
                for (int j = 0; j < 4; j++) acc[i][j] = fmaf(av[i], bv[j], acc[i][j]);
        }
        __syncthreads();
    }
#pragma unroll
    for (int i = 0; i < 4; i++)
        st(4 * ty + i, 4 * tx, make_float4(acc[i][0], acc[i][1], acc[i][2], acc[i][3]));
}

__device__ __forceinline__ void stage_a(uint32_t ab, const __nv_bfloat16* A0,
                                        const __nv_bfloat16* A1, int kg) {
    const int tid = threadIdx.x;
#pragma unroll
    for (int it = 0; it < 8; it++) {
        int id = tid + it * NT;
        int i = id >> 10, rem = id & 1023, r = rem >> 3, seg = rem & 7;
        const __nv_bfloat16* s = (i ? A1 : A0) + (size_t)r * HH + kg + seg * 8;
        cp16(ab + i * 16384 + r * 128 + ((seg ^ (r & 7)) << 4), s);
    }
    CP_COMMIT();
}

// one K=64 chunk, 3-term; 8 warps = 2M x 4N, warp tile 64x32
__device__ __forceinline__ void chunk_mma(float acc[4][4][4], uint32_t ab, uint32_t pb,
                                          int wm, int wn, int lane) {
#pragma unroll
    for (int kk = 0; kk < 4; kk++) {
        uint32_t af[2][4][4];
#pragma unroll
        for (int tm = 0; tm < 2; tm++)
#pragma unroll
            for (int mt = 0; mt < 4; mt++) {
                int row = wm * 64 + mt * 16 + (lane & 15);
                int ch = kk * 2 + (lane >> 4);
                LDSM4(af[tm][mt], ab + tm * 16384 + row * 128 + ((ch ^ (row & 7)) << 4));
            }
        uint32_t bf[2][8];
#pragma unroll
        for (int j = 0; j < 2; j++)
#pragma unroll
            for (int q = 0; q < 2; q++) {
                int nrow = wn * 32 + q * 16 + (lane & 7) + ((lane & 16) ? 8 : 0);
                int ch = kk * 2 + ((lane >> 3) & 1);
                LDSM4(&bf[j][q * 4], pb + j * 16384 + nrow * 128 + ((ch ^ (nrow & 7)) << 4));
            }
#pragma unroll
        for (int j = 0; j < 2; j++) {
            const int ni = (j == 0) ? 2 : 1;
#pragma unroll
            for (int i = 0; i < 2; i++) {
                if (i >= ni) break;
#pragma unroll
                for (int mt = 0; mt < 4; mt++)
#pragma unroll
                    for (int nt = 0; nt < 4; nt++) {
                        int q = nt >> 1, o = (nt & 1) * 2;
                        MMA16816(acc[mt][nt], af[i][mt], bf[j][q * 4 + o], bf[j][q * 4 + o + 1]);
                    }
            }
        }
    }
}

// full 128x128 K-sliced job: stage A, run nch chunks, store partials
__device__ __forceinline__ void run_job(const __nv_bfloat16* A0, const __nv_bfloat16* A1,
                                        int kbeg, int nch, uint32_t dyn,
                                        float* pdst, int pstride, int n0,
                                        int wm, int wn, int lane) {
    float acc[4][4][4];
#pragma unroll
    for (int a = 0; a < 4; a++)
#pragma unroll
        for (int b = 0; b < 4; b++)
#pragma unroll
            for (int c = 0; c < 4; c++) acc[a][b][c] = 0.f;
    stage_a(dyn + AB0, A0, A1, kbeg);
    if (nch > 1) stage_a(dyn + AB0 + ABSZ, A0, A1, kbeg + 64);
    for (int c = 0; c < nch; c++) {
        if (c + 1 < nch) { CP_WAIT1(); } else { CP_WAIT0(); }
        __syncthreads();
        chunk_mma(acc, dyn + AB0 + (c & 1) * ABSZ, dyn + c * BCH, wm, wn, lane);
        __syncthreads();
        if (c + 2 < nch) stage_a(dyn + AB0 + (c & 1) * ABSZ, A0, A1, kbeg + (c + 2) * 64);
    }
#pragma unroll
    for (int mt = 0; mt < 4; mt++)
#pragma unroll
        for (int nt = 0; nt < 4; nt++) {
            int r = wm * 64 + mt * 16 + (lane >> 2);
            int cc = wn * 32 + nt * 8 + (lane & 3) * 2;
            *(float2*)(pdst + (size_t)r * pstride + n0 + cc) =
                make_float2(acc[mt][nt][0], acc[mt][nt][1]);
            *(float2*)(pdst + (size_t)(r + 8) * pstride + n0 + cc) =
                make_float2(acc[mt][nt][2], acc[mt][nt][3]);
        }
}

__global__ void __launch_bounds__(NT, 1) rnn_mma_kernel(
    const int*   __restrict__ ids,   const float* __restrict__ emb,
    const float* __restrict__ w_xh0, const float* __restrict__ w_hh0,
    const float* __restrict__ b_h0,  const float* __restrict__ w_xh1,
    const float* __restrict__ w_hh1, const float* __restrict__ b_h1,
    const float* __restrict__ w_hy,  const float* __restrict__ b_y,
    float* __restrict__ out, long long out_size)
{
    extern __shared__ __align__(16) char dynsm[];
    const int bid = blockIdx.x;
    const int tid = threadIdx.x;
    const int lane = tid & 31;
    const int warp = tid >> 5;
    const int wm = warp >> 2, wn = warp & 3;
    const uint32_t dyn = (smem_u32(dynsm) + 1023u) & ~1023u;
    const long long full = (long long)BTV + 2LL * BH;

    unsigned long long epF = g_epF[bid];
    unsigned long long epA = g_epA[bid];
    unsigned long long epB = g_epB[bid];
    const unsigned long long h0base = g_h0base;
    const unsigned long long h1base = g_h1base;

    // ============ prologue (all blocks) ============
    {
        const float* W[4] = {w_hh0, w_xh1, w_hh1, w_hy};
        __nv_bfloat16* S0[4] = {g_w0sp[0], g_w1sp[0], g_w2sp[0], g_wysp[0]};
        __nv_bfloat16* S1[4] = {g_w0sp[1], g_w1sp[1], g_w2sp[1], g_wysp[1]};
        const int SZ[4] = {HH * HH, HH * HH, HH * HH, VV * HH};
#pragma unroll
        for (int w = 0; w < 4; w++)
            for (int i = bid * NT + tid; i < SZ[w]; i += NB * NT)
                split2(W[w][i], S0[w][i], S1[w][i]);
        for (int i = bid * NT + tid; i < BH; i += NB * NT) {
            g_h1sp[0][i] = __float2bfloat16(0.f);
            g_h1sp[1][i] = __float2bfloat16(0.f);
        }
    }
    {
        float* sA = (float*)dynsm;
        float* sB = sA + 32 * 68;
        int m0 = (bid & 7) * 64, n0t = (bid >> 3) * 64;
        gemm64(sA, sB, EE,
            [&](int r, int k) { return emb[(m0 + r) * EE + k]; },
            [&](int r, int k) { return w_xh0[(n0t + r) * EE + k]; },
            [&](int m, int n, float4 v) {
                int col = n0t + n;
                float4 bb = *(const float4*)(b_h0 + col);
                v.x += bb.x; v.y += bb.y; v.z += bb.z; v.w += bb.w;
                *(float4*)(g_tokproj + (size_t)(m0 + m) * HH + col) = v;
            });
    }
    gbar(g_brF, bid & 7, epF, NB);

    if (bid < 32) {
        // ================= PIPE A: h0 recurrence =================
        const int n0 = (bid & 7) * 128;
        const int kc = bid >> 3;
        const int kbeg = kc * 256;
        // persistent B = w_hh0 slice (4 chunks)
        for (int x = tid; x < 8192; x += NT) {
            int c = x >> 11, rem = x & 2047;
            int j = rem >> 10, r = (rem >> 3) & 127, seg = x & 7;
            const __nv_bfloat16* s = (j ? g_w0sp[1] : g_w0sp[0])
                + (size_t)(n0 + r) * HH + kbeg + c * 64 + seg * 8;
            uint4 v = *(const uint4*)s;
            STS128(dyn + c * BCH + j * 16384 + r * 128 + ((seg ^ (r & 7)) << 4),
                   v.x, v.y, v.z, v.w);
        }
        __syncthreads();

        for (int t = 0; t < TT; t++) {
            if (t >= 4) wait_ge(&g_h1done, h1base + (unsigned long long)(t - 3));
            // E0: finalize h0_t for rows bid*4 .. bid*4+3
            __nv_bfloat16* R0 = g_h0ring[t & 3][0];
            __nv_bfloat16* R1 = g_h0ring[t & 3][1];
#pragma unroll
            for (int it = 0; it < 4; it++) {
                int e4 = tid + it * NT;                  // 0..1023 float4 slots
                int row = bid * 4 + (e4 >> 8);
                int h = (e4 & 255) * 4;
                size_t idx = (size_t)row * HH + h;
                const int id_tok = ids[row * TT + t];
                float4 s = *(const float4*)(g_tokproj + (size_t)id_tok * HH + h);
                if (t > 0) {
#pragma unroll
                    for (int k = 0; k < 4; k++) {
                        float4 p = __ldcg((const float4*)&g_P0p[k][idx]);
                        s.x += p.x; s.y += p.y; s.z += p.z; s.w += p.w;
                    }
                }
                float4 v;
                v.x = tanhf(s.x); v.y = tanhf(s.y); v.z = tanhf(s.z); v.w = tanhf(s.w);
                st_split4(R0, R1, idx, v);
                if (t == TT - 1 && out_size >= full) *(float4*)&out[BTV + idx] = v;
            }
            gbar(g_brA, bid & 7, epA, 32);
            if (bid == 0 && tid == 0) atomicAdd(&g_h0done, 1ULL);
            // G0: P0 = h0_t @ w_hh0^T (for t+1)
            if (t <= TT - 2)
                run_job(g_h0ring[t & 3][0], g_h0ring[t & 3][1], kbeg, 4, dyn,
                        g_P0p[kc], HH, n0, wm, wn, lane);
            gbar(g_brA, bid & 7, epA, 32);
        }
    } else {
        // ================= PIPE B: h1 chain + logits =================
        const int j = bid - 32;
        const int grp = j >> 5;                 // 0:P1a 1:P1b 2:Py
        int n0, kbeg, nch, pstride;
        const __nv_bfloat16 *Bs0, *Bs1;
        float* pdst;
        if (grp == 0) {
            n0 = (j & 7) * 128; int kc = (j >> 3) & 3;
            kbeg = kc * 256; nch = 4; Bs0 = g_w1sp[0]; Bs1 = g_w1sp[1];
            pdst = g_P1p[kc]; pstride = HH;
        } else if (grp == 1) {
            int jj = j - 32; n0 = (jj & 7) * 128; int kc = (jj >> 3) & 3;
            kbeg = kc * 256; nch = 4; Bs0 = g_w2sp[0]; Bs1 = g_w2sp[1];
            pdst = g_P1p[4 + kc]; pstride = HH;
        } else {
            int jj = j - 64; n0 = (jj & 3) * 128; int kc = jj >> 2;
            kbeg = kc * 128; nch = 2; Bs0 = g_wysp[0]; Bs1 = g_wysp[1];
            pdst = g_Py[kc]; pstride = VV;
        }
        // E-row assignment: 96 blocks cover 128 batch rows (first 32 get 2 rows)
        const int r0 = (j < 32) ? j * 2 : 64 + (j - 32);
        const int nrows = (j < 32) ? 2 : 1;
        // persistent B slabs
        for (int x = tid; x < nch * 2048; x += NT) {
            int c = x >> 11, rem = x & 2047;
            int jt = rem >> 10, r = (rem >> 3) & 127, seg = x & 7;
            const __nv_bfloat16* s = (jt ? Bs1 : Bs0)
                + (size_t)(n0 + r) * HH + kbeg + c * 64 + seg * 8;
            uint4 v = *(const uint4*)s;
            STS128(dyn + c * BCH + jt * 16384 + r * 128 + ((seg ^ (r & 7)) << 4),
                   v.x, v.y, v.z, v.w);
        }
        __syncthreads();

        for (int t = 0; t <= TT + 1; t++) {
            // E1: finalize h1_{t-1}; logits row t-2
            if (t >= 1 && t <= TT) {
                const int nf4 = nrows * 256;             // float4 slots
                for (int e4 = tid; e4 < nf4; e4 += NT) {
                    int row = r0 + (e4 >> 8);
                    int h = (e4 & 255) * 4;
                    size_t idx = (size_t)row * HH + h;
                    float4 s = *(const float4*)(b_h1 + h);
#pragma unroll
                    for (int k = 0; k < 8; k++) {
                        float4 p = __ldcg((const float4*)&g_P1p[k][idx]);
                        s.x += p.x; s.y += p.y; s.z += p.z; s.w += p.w;
                    }
                    float4 v;
                    v.x = tanhf(s.x); v.y = tanhf(s.y); v.z = tanhf(s.z); v.w = tanhf(s.w);
                    st_split4(g_h1sp[0], g_h1sp[1], idx, v);
                    if (t == TT && out_size >= full) *(float4*)&out[BTV + BH + idx] = v;
                }
            }
            if (t >= 2) {
                const int nf4 = nrows * 128;             // float4 slots over VV
                for (int e4 = tid; e4 < nf4; e4 += NT) {
                    int row = r0 + (e4 >> 7);
                    int v0 = (e4 & 127) * 4;
                    size_t pidx = (size_t)row * VV + v0;
                    float4 r = *(const float4*)(b_y + v0);
#pragma unroll
                    for (int k = 0; k < 8; k++) {
                        float4 p = __ldcg((const float4*)&g_Py[k][pidx]);
                        r.x += p.x; r.y += p.y; r.z += p.z; r.w += p.w;
                    }
                    *(float4*)&out[((size_t)row * TT + (t - 2)) * VV + v0] = r;
                }
            }
            gbar(g_brB, j & 7, epB, 96);
            // G1
            if (grp == 0) {
                if (t <= TT - 1) {
                    wait_ge(&g_h0done, h0base + (unsigned long long)(t + 1));
                    run_job(g_h0ring[t & 3][0], g_h0ring[t & 3][1], kbeg, nch, dyn,
                            pdst, pstride, n0, wm, wn, lane);
                }
            } else if (grp == 1) {
                if (t <= TT - 1)
                    run_job(g_h1sp[0], g_h1sp[1], kbeg, nch, dyn,
                            pdst, pstride, n0, wm, wn, lane);
            } else {
                if (t >= 1 && t <= TT)
                    run_job(g_h1sp[0], g_h1sp[1], kbeg, nch, dyn,
                            pdst, pstride, n0, wm, wn, lane);
            }
            gbar(g_brB, j & 7, epB, 96);
            if (bid == 32 && tid == 0) atomicAdd(&g_h1done, 1ULL);
        }
    }

    // ============ epilogue ============
    gbar(g_brF, bid & 7, epF, NB);
    if (bid == 0 && tid == 0) {
        g_h0base = h0base + (unsigned long long)TT;
        g_h1base = h1base + (unsigned long long)(TT + 2);
    }
    if (tid == 0) {
        g_epF[bid] = epF;
        g_epA[bid] = epA;
        g_epB[bid] = epB;
    }
}

extern "C" void kernel_launch(void* const* d_in, const int* in_sizes, int n_in,
                              void* d_out, int out_size) {
    const int*   ids   = (const int*)d_in[0];
    const float* emb   = (const float*)d_in[1];
    const float* w_xh0 = (const float*)d_in[2];
    const float* w_hh0 = (const float*)d_in[3];
    const float* b_h0  = (const float*)d_in[4];
    const float* w_xh1 = (const float*)d_in[5];
    const float* w_hh1 = (const float*)d_in[6];
    const float* b_h1  = (const float*)d_in[7];
    const float* w_hy  = (const float*)d_in[8];
    const float* b_y   = (const float*)d_in[9];
    float* out = (float*)d_out;

    cudaFuncSetAttribute(rnn_mma_kernel, cudaFuncAttributeMaxDynamicSharedMemorySize,
                         DYNB_ALLOC);
    rnn_mma_kernel<<<NB, NT, DYNB_ALLOC>>>(ids, emb, w_xh0, w_hh0, b_h0,
                                           w_xh1, w_hh1, b_h1, w_hy, b_y,
                                           out, (long long)out_size);
}